// round 6
// baseline (speedup 1.0000x reference)
#include <cuda_runtime.h>
#include <cuda_bf16.h>
#include <math.h>
#include <stdint.h>

// pred[b] = sigmoid(gb + data[b,:].bias + || data[b,:] @ embed ||^2)
//   (the (B,F,F) Gram double-sum collapses to the squared norm of s = x @ V)
//
// Cluster design: grid = 8 clusters x 8 CTAs (64 CTAs, one wave), 256 thr.
// Cluster bg owns batch rows [bg*8, bg*8+8); CTA rank fg owns features
// [fg*256, fg*256+256) x all 64 dims.
//   - x tile in smem; butterfly (SHFL.XOR) reduces the 16 feature slices
//   - per-CTA partial s[8][64] + lin[8] stay in LOCAL smem (no atomics,
//     no global scratch, no reset -> trivially graph-replay deterministic)
//   - one cluster.sync, then CTA rank r sums the 8 partials for batch row r
//     via ld.shared::cluster (DSMEM) and writes out[bg*8 + r].

#define F_NUM   2048
#define D_DIM   64
#define BATCH   64
#define THREADS 256
#define BGC     8          // clusters (batch groups of 8 rows)
#define CSZ     8          // CTAs per cluster (feature slices)
#define FPB     256        // features per CTA
#define BPB     8          // batch rows per cluster

__device__ __forceinline__ uint32_t smem_u32(const void* p) {
    return (uint32_t)__cvta_generic_to_shared(p);
}
__device__ __forceinline__ float ld_dsmem_f32(uint32_t laddr, uint32_t rank) {
    uint32_t r; float v;
    asm volatile("mapa.shared::cluster.u32 %0, %1, %2;" : "=r"(r) : "r"(laddr), "r"(rank));
    asm volatile("ld.shared::cluster.f32 %0, [%1];" : "=f"(v) : "r"(r));
    return v;
}

__global__ __launch_bounds__(THREADS, 1) __cluster_dims__(CSZ, 1, 1)
void KTM_22110491640579_kernel(const float* __restrict__ data,
                               const float* __restrict__ embed,
                               const float* __restrict__ bias,
                               const float* __restrict__ gbias,
                               float* __restrict__ out) {
    __shared__ float4 xs4[BPB][FPB / 4];   // 8 KB: x tile [8][256]
    __shared__ float4 part4[BPB][16];      // 2 KB: partial s for 8 rows
    __shared__ float  plin[BPB];           // partial linear term

    const int tid  = threadIdx.x;
    const int w    = tid >> 5;             // warp 0..7
    const int lane = tid & 31;
    const int fg   = blockIdx.x;           // == cluster rank, 0..7
    const int bg   = blockIdx.y;           // cluster id, 0..7
    const int f0   = fg * FPB;
    const int b0   = bg * BPB;

    // ---- prefetch bias slice (overlaps x staging) ----
    float bv[8];
    #pragma unroll
    for (int k = 0; k < 8; ++k) bv[k] = bias[f0 + lane + 32 * k];

    // ---- stage x tile: warp w = batch row w, 64 float4 per row ----
    {
        const float4* src = (const float4*)(data + (size_t)(b0 + w) * F_NUM + f0);
        xs4[w][lane]      = src[lane];
        xs4[w][lane + 32] = src[lane + 32];
    }
    __syncthreads();
    const float* xs = (const float*)xs4;   // [b][f], stride 256

    // ---- main loop ----
    // dq = half-warp quad of the 64-dim s vector; fs = lane bits 0..3 -> 16
    // slices of 16 features each.
    const int dq = (w << 1) | (lane >> 4); // 0..15
    const int fs = lane & 15;              // 0..15
    const float4* V4 = ((const float4*)embed) + ((size_t)(f0 + fs * 16) * 16 + dq);

    float4 acc[BPB];
    #pragma unroll
    for (int b = 0; b < BPB; ++b) acc[b] = make_float4(0.f, 0.f, 0.f, 0.f);

    #pragma unroll
    for (int j = 0; j < 16; ++j) {
        const float4 v = V4[(size_t)j * 16];            // L2-hot
        #pragma unroll
        for (int b = 0; b < BPB; ++b) {
            const float x = xs[b * FPB + fs * 16 + j];  // smem
            acc[b].x = fmaf(x, v.x, acc[b].x);
            acc[b].y = fmaf(x, v.y, acc[b].y);
            acc[b].z = fmaf(x, v.z, acc[b].z);
            acc[b].w = fmaf(x, v.w, acc[b].w);
        }
    }

    // ---- linear term: warp w = batch row w ----
    {
        float l = 0.f;
        #pragma unroll
        for (int k = 0; k < 8; ++k)
            l = fmaf(xs[w * FPB + lane + 32 * k], bv[k], l);
        #pragma unroll
        for (int off = 16; off >= 1; off >>= 1)
            l += __shfl_down_sync(0xffffffffu, l, off);
        if (lane == 0) plin[w] = l;
    }

    // ---- butterfly over fs (lane bits 0..3); every lane gets full fs-sum ----
    #pragma unroll
    for (int off = 1; off < 16; off <<= 1) {
        #pragma unroll
        for (int b = 0; b < BPB; ++b) {
            acc[b].x += __shfl_xor_sync(0xffffffffu, acc[b].x, off);
            acc[b].y += __shfl_xor_sync(0xffffffffu, acc[b].y, off);
            acc[b].z += __shfl_xor_sync(0xffffffffu, acc[b].z, off);
            acc[b].w += __shfl_xor_sync(0xffffffffu, acc[b].w, off);
        }
    }
    // 8 lanes per half-warp each store one batch row's quad into local smem.
    if (fs < BPB) part4[fs][dq] = acc[fs];

    // ---- cluster barrier: all CTAs' part4/plin become visible ----
    asm volatile("barrier.cluster.arrive.aligned;" ::: "memory");
    asm volatile("barrier.cluster.wait.aligned;"   ::: "memory");

    // ---- finish: this CTA computes batch row r = fg via DSMEM gather ----
    if (w == 0) {
        const float* part_f = (const float*)part4;       // [8][64]
        const uint32_t a_lo = smem_u32(&part_f[fg * D_DIM + lane]);
        const uint32_t a_hi = smem_u32(&part_f[fg * D_DIM + lane + 32]);
        float s_lo = 0.f, s_hi = 0.f;
        #pragma unroll
        for (uint32_t c = 0; c < CSZ; ++c) {
            s_lo += ld_dsmem_f32(a_lo, c);
            s_hi += ld_dsmem_f32(a_hi, c);
        }
        float a = s_lo * s_lo + s_hi * s_hi;             // ||s||^2 partial
        if (lane < CSZ)                                  // lin partial from CTA 'lane'
            a += ld_dsmem_f32(smem_u32(&plin[fg]), (uint32_t)lane);
        #pragma unroll
        for (int off = 16; off >= 1; off >>= 1)
            a += __shfl_down_sync(0xffffffffu, a, off);
        if (lane == 0) {
            const float z = gbias[0] + a;
            out[b0 + fg] = 1.0f / (1.0f + __expf(-z));
        }
    }

    // ---- keep smem alive until every CTA finished its remote reads ----
    asm volatile("barrier.cluster.arrive.aligned;" ::: "memory");
    asm volatile("barrier.cluster.wait.aligned;"   ::: "memory");
}

extern "C" void kernel_launch(void* const* d_in, const int* in_sizes, int n_in,
                              void* d_out, int out_size) {
    const float* data  = (const float*)d_in[0];   // (64, 2048)
    const float* embed = (const float*)d_in[1];   // (2048, 64)
    const float* bias  = (const float*)d_in[2];   // (2048, 1)
    const float* gb    = (const float*)d_in[3];   // (1, 1)
    float* out = (float*)d_out;                   // (64,)
    (void)in_sizes; (void)n_in; (void)out_size;

    dim3 grid(CSZ, BGC);                          // 8 CTAs/cluster x 8 clusters
    KTM_22110491640579_kernel<<<grid, THREADS>>>(data, embed, bias, gb, out);
}